// round 1
// baseline (speedup 1.0000x reference)
#include <cuda_runtime.h>
#include <cstdint>

// Problem constants
#define BB 128
#define TT 512
#define HALF 256
#define DD 512
#define G3D 1536
#define MROWS 32768   // BB*HALF
#define NC 7

typedef unsigned long long ull;

// ---------------- scratch (static device allocations; no cudaMalloc) ----------------
__device__ float g_gx[(size_t)HALF * BB * G3D];   // [256,128,1536] input-gate preacts (incl b_ih)
__device__ float g_P [(size_t)MROWS * DD];        // emotions, row = b*256+t
__device__ float g_t1[(size_t)MROWS * DD];
__device__ float g_t2[(size_t)MROWS * DD];
__device__ float g_h4[(size_t)MROWS * (DD/2)];
__device__ float g_lse[MROWS];
__device__ float g_s[DD/2];
__device__ float g_h[2 * BB * DD];                // ping-pong hidden state

// ---------------- f32x2 helpers (full-rate fp32 on Blackwell) ----------------
__device__ __forceinline__ void ffma2(ull &d, ull a, ull b) {
    asm("fma.rn.f32x2 %0, %1, %2, %0;" : "+l"(d) : "l"(a), "l"(b));
}
__device__ __forceinline__ ull dup2(float x) {
    ull r; asm("mov.b64 %0, {%1, %1};" : "=l"(r) : "f"(x)); return r;
}
__device__ __forceinline__ float2 un2(ull v) {
    float2 f; asm("mov.b64 {%0, %1}, %2;" : "=f"(f.x), "=f"(f.y) : "l"(v)); return f;
}

// ---------------- generic 128x128 fp32 GEMM: C[M,N] = A[M,K] @ W[N,K]^T (+bias, act) ----
// MODE_A: 0 = A row-major contiguous (lda=K)
//         1 = A is x0[B,T,D]; logical row r -> b = r%128, t = r/128, ptr = A + (b*T + t)*D
// ACT: 0 = +bias ; 1 = tanh(+bias) ; 3 = +bias - lse[row]*s[col]  (folded log_softmax)
template<int MODE_A, int ACT>
__global__ __launch_bounds__(256)
void gemm_kernel(const float* __restrict__ A, const float* __restrict__ W,
                 const float* __restrict__ bias, float* __restrict__ C,
                 int M, int N, int K,
                 const float* __restrict__ lse, const float* __restrict__ svec)
{
    __shared__ float As[16 * 132];
    __shared__ float Bs[16 * 132];
    const int tid = threadIdx.x;
    const int tx = tid & 15, ty = tid >> 4;
    const int m0 = blockIdx.y * 128;
    const int n0 = blockIdx.x * 128;

    ull acc[8][4];
#pragma unroll
    for (int i = 0; i < 8; i++)
#pragma unroll
        for (int j = 0; j < 4; j++) acc[i][j] = 0ull;

    int lrow[2], lc4[2];
    const float* aptr[2];
    const float* wptr[2];
#pragma unroll
    for (int j = 0; j < 2; j++) {
        int f = tid + j * 256;
        lrow[j] = f >> 2; lc4[j] = f & 3;
        int gr = m0 + lrow[j];
        if (MODE_A == 1) {
            int b = gr & 127, t = gr >> 7;
            aptr[j] = A + ((size_t)b * TT + t) * DD;
        } else {
            aptr[j] = A + (size_t)gr * K;
        }
        wptr[j] = W + (size_t)(n0 + lrow[j]) * K;
    }

    for (int kt = 0; kt < K; kt += 16) {
        float4 av[2], bv[2];
#pragma unroll
        for (int j = 0; j < 2; j++) {
            av[j] = *(const float4*)(aptr[j] + kt + lc4[j] * 4);
            bv[j] = *(const float4*)(wptr[j] + kt + lc4[j] * 4);
        }
        __syncthreads();
#pragma unroll
        for (int j = 0; j < 2; j++) {
            int k0 = lc4[j] * 4;
            float* as = &As[k0 * 132 + lrow[j]];
            as[0] = av[j].x; as[132] = av[j].y; as[264] = av[j].z; as[396] = av[j].w;
            float* bs = &Bs[k0 * 132 + lrow[j]];
            bs[0] = bv[j].x; bs[132] = bv[j].y; bs[264] = bv[j].z; bs[396] = bv[j].w;
        }
        __syncthreads();
#pragma unroll
        for (int k = 0; k < 16; k++) {
            float4 a0 = *(const float4*)&As[k * 132 + ty * 8];
            float4 a1 = *(const float4*)&As[k * 132 + ty * 8 + 4];
            const ull* bp = (const ull*)&Bs[k * 132 + tx * 8];
            ull b2[4] = { bp[0], bp[1], bp[2], bp[3] };
            ull ad[8] = { dup2(a0.x), dup2(a0.y), dup2(a0.z), dup2(a0.w),
                          dup2(a1.x), dup2(a1.y), dup2(a1.z), dup2(a1.w) };
#pragma unroll
            for (int i = 0; i < 8; i++)
#pragma unroll
                for (int j = 0; j < 4; j++)
                    ffma2(acc[i][j], ad[i], b2[j]);
        }
    }

#pragma unroll
    for (int i = 0; i < 8; i++) {
        int row = m0 + ty * 8 + i;
        float lsev = (ACT == 3) ? lse[row] : 0.f;
#pragma unroll
        for (int j = 0; j < 4; j++) {
            float2 v = un2(acc[i][j]);
            int col = n0 + tx * 8 + j * 2;
            v.x += bias[col]; v.y += bias[col + 1];
            if (ACT == 1) { v.x = tanhf(v.x); v.y = tanhf(v.y); }
            if (ACT == 3) { v.x -= lsev * svec[col]; v.y -= lsev * svec[col + 1]; }
            *(float2*)&C[(size_t)row * N + col] = v;
        }
    }
}

// ---------------- GRU step: one launch per t (graph nodes; kernel boundary = sync) -----
// grid (8 batch-groups x 16 unit-slices), 256 threads.
// thread = (rp = warp id -> 2 batch rows, u = lane -> 1 hidden unit, all 3 gates)
__global__ __launch_bounds__(256)
void gru_step_kernel(const float* __restrict__ hprev, float* __restrict__ hnext,
                     const float* __restrict__ gx_t, const float* __restrict__ Whh,
                     const float* __restrict__ bhh, float* __restrict__ P, int t)
{
    extern __shared__ float sm[];
    float* ht = sm;               // [16][512]   h tile for this batch group
    float* Ws = sm + 16 * 512;    // [96][66]    W_hh chunk (row = u*3+g), stride 66 vs bank conflicts
    const int tid = threadIdx.x;
    const int u = tid & 31, rp = tid >> 5;
    const int bx = blockIdx.x;    // batch group (16 rows)
    const int uy = blockIdx.y;    // unit slice (32 units)

    // load h tile [16][512] (fully coalesced float4)
#pragma unroll
    for (int i = 0; i < 8; i++) {
        int f = tid + i * 256;
        int row = f >> 7, c4 = f & 127;
        *(float4*)&ht[row * 512 + c4 * 4] =
            *(const float4*)&hprev[(size_t)(bx * 16 + row) * 512 + c4 * 4];
    }

    ull acc[2][3] = {};
    for (int kc = 0; kc < 512; kc += 64) {
        // stream W_hh chunk: 96 rows x 64 cols
#pragma unroll
        for (int i = 0; i < 12; i++) {
            int f = tid + i * 256;
            int row = f >> 5, c2 = f & 31;       // row < 96
            int uu = row / 3, g = row - uu * 3;
            *(float2*)&Ws[row * 66 + c2 * 2] =
                *(const float2*)&Whh[(size_t)(g * 512 + uy * 32 + uu) * 512 + kc + c2 * 2];
        }
        __syncthreads();
#pragma unroll 8
        for (int kk = 0; kk < 64; kk += 2) {
            ull h0 = *(const ull*)&ht[(rp * 2    ) * 512 + kc + kk];
            ull h1 = *(const ull*)&ht[(rp * 2 + 1) * 512 + kc + kk];
            ull w0 = *(const ull*)&Ws[(u * 3 + 0) * 66 + kk];
            ull w1 = *(const ull*)&Ws[(u * 3 + 1) * 66 + kk];
            ull w2 = *(const ull*)&Ws[(u * 3 + 2) * 66 + kk];
            ffma2(acc[0][0], h0, w0); ffma2(acc[0][1], h0, w1); ffma2(acc[0][2], h0, w2);
            ffma2(acc[1][0], h1, w0); ffma2(acc[1][1], h1, w1); ffma2(acc[1][2], h1, w2);
        }
        __syncthreads();
    }

    const int d = uy * 32 + u;
    const float bh0 = bhh[d], bh1 = bhh[512 + d], bh2 = bhh[1024 + d];
#pragma unroll
    for (int rl = 0; rl < 2; rl++) {
        int row = rp * 2 + rl;
        int grow = bx * 16 + row;                 // global batch index b
        float2 f0 = un2(acc[rl][0]), f1 = un2(acc[rl][1]), f2 = un2(acc[rl][2]);
        float hr = f0.x + f0.y + bh0;
        float hz = f1.x + f1.y + bh1;
        float hn = f2.x + f2.y + bh2;
        const float* gxp = gx_t + (size_t)grow * G3D + d;
        float xr = gxp[0], xz = gxp[512], xn = gxp[1024];
        float rg = 1.f / (1.f + expf(-(xr + hr)));
        float zg = 1.f / (1.f + expf(-(xz + hz)));
        float ng = tanhf(xn + rg * hn);
        float hp = ht[row * 512 + d];
        float hnew = (1.f - zg) * ng + zg * hp;
        hnext[(size_t)grow * 512 + d] = hnew;
        P[((size_t)grow * 256 + t) * 512 + d] = hnew;
    }
}

// ---------------- small kernels ----------------
__global__ void init_kernel(float* h0) {
    int i = blockIdx.x * blockDim.x + threadIdx.x;   // 16384 threads
    float4 z = {0.f, 0.f, 0.f, 0.f};
    *(float4*)&h0[i * 4] = z;
}

__global__ __launch_bounds__(256)
void lse_kernel(const float* __restrict__ X, float* __restrict__ lse) {
    int warp = threadIdx.x >> 5, lane = threadIdx.x & 31;
    int row = blockIdx.x * 8 + warp;
    const float* x = X + (size_t)row * 512;
    float v[16];
#pragma unroll
    for (int i = 0; i < 4; i++) {
        float4 f = *(const float4*)&x[lane * 4 + i * 128];
        v[i * 4 + 0] = f.x; v[i * 4 + 1] = f.y; v[i * 4 + 2] = f.z; v[i * 4 + 3] = f.w;
    }
    float m = v[0];
#pragma unroll
    for (int i = 1; i < 16; i++) m = fmaxf(m, v[i]);
#pragma unroll
    for (int o = 16; o; o >>= 1) m = fmaxf(m, __shfl_xor_sync(0xffffffffu, m, o));
    float s = 0.f;
#pragma unroll
    for (int i = 0; i < 16; i++) s += expf(v[i] - m);
#pragma unroll
    for (int o = 16; o; o >>= 1) s += __shfl_xor_sync(0xffffffffu, s, o);
    if (lane == 0) lse[row] = m + logf(s);
}

__global__ void ssum_kernel(const float* __restrict__ Wh, float* __restrict__ s) {
    int j = threadIdx.x;   // 256
    float acc = 0.f;
    for (int k = 0; k < 512; k++) acc += Wh[(size_t)j * 512 + k];
    s[j] = acc;
}

__global__ __launch_bounds__(256)
void head_kernel(const float* __restrict__ H, const float* __restrict__ Wout,
                 const float* __restrict__ bout, float* __restrict__ out) {
    __shared__ float Ws[7][256];
    int tid = threadIdx.x;
    for (int f = tid; f < 7 * 256; f += 256) Ws[f >> 8][f & 255] = Wout[f];
    __syncthreads();
    int warp = tid >> 5, lane = tid & 31;
    int row = blockIdx.x * 8 + warp;
    const float* h = H + (size_t)row * 256;
    float hv[8];
    *(float4*)&hv[0] = *(const float4*)&h[lane * 8];
    *(float4*)&hv[4] = *(const float4*)&h[lane * 8 + 4];
#pragma unroll
    for (int c = 0; c < 7; c++) {
        float a = 0.f;
#pragma unroll
        for (int j = 0; j < 8; j++) a += hv[j] * Ws[c][lane * 8 + j];
#pragma unroll
        for (int o = 16; o; o >>= 1) a += __shfl_xor_sync(0xffffffffu, a, o);
        if (lane == c) out[(size_t)row * 7 + c] = a + bout[c];
    }
}

// ---------------- launch ----------------
extern "C" void kernel_launch(void* const* d_in, const int* in_sizes, int n_in,
                              void* d_out, int out_size)
{
    const float* x0   = (const float*)d_in[0];
    const float* W_ih = (const float*)d_in[3];
    const float* W_hh = (const float*)d_in[4];
    const float* b_ih = (const float*)d_in[5];
    const float* b_hh = (const float*)d_in[6];
    const float* W1   = (const float*)d_in[7];
    const float* b1   = (const float*)d_in[8];
    const float* W2   = (const float*)d_in[9];
    const float* b2   = (const float*)d_in[10];
    const float* W3   = (const float*)d_in[11];
    const float* b3   = (const float*)d_in[12];
    const float* Wh   = (const float*)d_in[13];
    const float* bh   = (const float*)d_in[14];
    const float* Wo   = (const float*)d_in[15];
    const float* bo   = (const float*)d_in[16];
    float* out = (float*)d_out;

    float *gx, *P, *t1, *t2, *h4, *lse, *s, *hbuf;
    cudaGetSymbolAddress((void**)&gx,  g_gx);
    cudaGetSymbolAddress((void**)&P,   g_P);
    cudaGetSymbolAddress((void**)&t1,  g_t1);
    cudaGetSymbolAddress((void**)&t2,  g_t2);
    cudaGetSymbolAddress((void**)&h4,  g_h4);
    cudaGetSymbolAddress((void**)&lse, g_lse);
    cudaGetSymbolAddress((void**)&s,   g_s);
    cudaGetSymbolAddress((void**)&hbuf, g_h);

    const int GRU_SMEM = (16 * 512 + 96 * 66) * 4;   // 58112 B
    cudaFuncSetAttribute(gru_step_kernel, cudaFuncAttributeMaxDynamicSharedMemorySize, GRU_SMEM);

    // h0 = 0
    init_kernel<<<64, 256>>>(hbuf);

    // gx = x0[:, :256, :] @ W_ih^T + b_ih   (rows ordered r = t*128 + b)
    gemm_kernel<1, 0><<<dim3(12, 256), 256>>>(x0, W_ih, b_ih, gx, MROWS, G3D, DD, nullptr, nullptr);

    // GRU recurrence, 256 steps (each launch = one step; graph handles dispatch)
    for (int t = 0; t < HALF; t++) {
        const float* hp = hbuf + (t & 1) * (BB * DD);
        float*       hn = hbuf + ((t + 1) & 1) * (BB * DD);
        gru_step_kernel<<<dim3(8, 16), 256, GRU_SMEM>>>(hp, hn, gx + (size_t)t * BB * G3D,
                                                        W_hh, b_hh, P, t);
    }

    // FFN
    gemm_kernel<0, 1><<<dim3(4, 256), 256>>>(P,  W1, b1, t1, MROWS, DD, DD, nullptr, nullptr);
    gemm_kernel<0, 1><<<dim3(4, 256), 256>>>(t1, W2, b2, t2, MROWS, DD, DD, nullptr, nullptr);
    gemm_kernel<0, 0><<<dim3(4, 256), 256>>>(t2, W3, b3, t1, MROWS, DD, DD, nullptr, nullptr);

    // folded log_softmax + half head
    lse_kernel<<<4096, 256>>>(t1, lse);
    ssum_kernel<<<1, 256>>>(Wh, s);
    gemm_kernel<0, 3><<<dim3(2, 256), 256>>>(t1, Wh, bh, h4, MROWS, DD / 2, DD, lse, s);

    // final head -> out [32768, 7]
    head_kernel<<<4096, 256>>>(h4, Wo, bo, out);
}

// round 3
// speedup vs baseline: 1.3130x; 1.3130x over previous
#include <cuda_runtime.h>
#include <cstdint>

// Problem constants
#define BB 128
#define TT 512
#define HALF 256
#define DD 512
#define G3D 1536
#define MROWS 32768   // BB*HALF
#define GRID_GRU 128

#define HT_STRIDE 516
#define W_STRIDE  514

typedef unsigned long long ull;

// ---------------- scratch (static device allocations; no cudaMalloc) ----------------
__device__ float g_gx[(size_t)HALF * BB * G3D];   // [256,128,1536] input preacts (incl b_ih)
__device__ float g_P [(size_t)MROWS * DD];        // emotions, row = b*256+t
__device__ float g_t1[(size_t)MROWS * DD];
__device__ float g_t2[(size_t)MROWS * DD];
__device__ float g_h4[(size_t)MROWS * (DD/2)];
__device__ float g_lse[MROWS];
__device__ float g_s[DD/2];
__device__ float g_h[2 * BB * DD];                // ping-pong hidden state
__device__ unsigned g_arrive;
__device__ unsigned g_gen;

// ---------------- f32x2 helpers ----------------
__device__ __forceinline__ void ffma2(ull &d, ull a, ull b) {
    asm("fma.rn.f32x2 %0, %1, %2, %0;" : "+l"(d) : "l"(a), "l"(b));
}
__device__ __forceinline__ ull dup2(float x) {
    ull r; asm("mov.b64 %0, {%1, %1};" : "=l"(r) : "f"(x)); return r;
}
__device__ __forceinline__ float2 un2(ull v) {
    float2 f; asm("mov.b64 {%0, %1}, %2;" : "=f"(f.x), "=f"(f.y) : "l"(v)); return f;
}

// ---------------- generic 128x128 fp32 GEMM: C[M,N] = A[M,K] @ W[N,K]^T ----------------
// MODE_A: 0 = A row-major (lda=K); 1 = A is x0[B,T,D], logical row r -> b=r%128, t=r/128
// ACT: 0 = +bias ; 1 = tanh(+bias) ; 3 = +bias - lse[row]*s[col]
template<int MODE_A, int ACT>
__global__ __launch_bounds__(256)
void gemm_kernel(const float* __restrict__ A, const float* __restrict__ W,
                 const float* __restrict__ bias, float* __restrict__ C,
                 int M, int N, int K,
                 const float* __restrict__ lse, const float* __restrict__ svec)
{
    __shared__ float As[16 * 132];
    __shared__ float Bs[16 * 132];
    const int tid = threadIdx.x;
    const int tx = tid & 15, ty = tid >> 4;
    const int m0 = blockIdx.y * 128;
    const int n0 = blockIdx.x * 128;

    ull acc[8][4];
#pragma unroll
    for (int i = 0; i < 8; i++)
#pragma unroll
        for (int j = 0; j < 4; j++) acc[i][j] = 0ull;

    int lrow[2], lc4[2];
    const float* aptr[2];
    const float* wptr[2];
#pragma unroll
    for (int j = 0; j < 2; j++) {
        int f = tid + j * 256;
        lrow[j] = f >> 2; lc4[j] = f & 3;
        int gr = m0 + lrow[j];
        if (MODE_A == 1) {
            int b = gr & 127, t = gr >> 7;
            aptr[j] = A + ((size_t)b * TT + t) * DD;
        } else {
            aptr[j] = A + (size_t)gr * K;
        }
        wptr[j] = W + (size_t)(n0 + lrow[j]) * K;
    }

    for (int kt = 0; kt < K; kt += 16) {
        float4 av[2], bv[2];
#pragma unroll
        for (int j = 0; j < 2; j++) {
            av[j] = *(const float4*)(aptr[j] + kt + lc4[j] * 4);
            bv[j] = *(const float4*)(wptr[j] + kt + lc4[j] * 4);
        }
        __syncthreads();
#pragma unroll
        for (int j = 0; j < 2; j++) {
            int k0 = lc4[j] * 4;
            float* as = &As[k0 * 132 + lrow[j]];
            as[0] = av[j].x; as[132] = av[j].y; as[264] = av[j].z; as[396] = av[j].w;
            float* bs = &Bs[k0 * 132 + lrow[j]];
            bs[0] = bv[j].x; bs[132] = bv[j].y; bs[264] = bv[j].z; bs[396] = bv[j].w;
        }
        __syncthreads();
#pragma unroll
        for (int k = 0; k < 16; k++) {
            float4 a0 = *(const float4*)&As[k * 132 + ty * 8];
            float4 a1 = *(const float4*)&As[k * 132 + ty * 8 + 4];
            const ull* bp = (const ull*)&Bs[k * 132 + tx * 8];
            ull b2[4] = { bp[0], bp[1], bp[2], bp[3] };
            ull ad[8] = { dup2(a0.x), dup2(a0.y), dup2(a0.z), dup2(a0.w),
                          dup2(a1.x), dup2(a1.y), dup2(a1.z), dup2(a1.w) };
#pragma unroll
            for (int i = 0; i < 8; i++)
#pragma unroll
                for (int j = 0; j < 4; j++)
                    ffma2(acc[i][j], ad[i], b2[j]);
        }
    }

#pragma unroll
    for (int i = 0; i < 8; i++) {
        int row = m0 + ty * 8 + i;
        float lsev = (ACT == 3) ? lse[row] : 0.f;
#pragma unroll
        for (int j = 0; j < 4; j++) {
            float2 v = un2(acc[i][j]);
            int col = n0 + tx * 8 + j * 2;
            v.x += bias[col]; v.y += bias[col + 1];
            if (ACT == 1) { v.x = tanhf(v.x); v.y = tanhf(v.y); }
            if (ACT == 3) { v.x -= lsev * svec[col]; v.y -= lsev * svec[col + 1]; }
            *(float2*)&C[(size_t)row * N + col] = v;
        }
    }
}

// ---------------- persistent GRU kernel: all 256 steps in one launch ----------------
// Grid 128 = 4 batch-groups (32 rows) x 32 unit-groups (16 units = 48 gate-rows).
// W slice lives in smem across all steps. 8 warps split K=512 (64 each); each warp
// computes the full 32x48 tile on its k-slice; partials reduced in smem.
__global__ __launch_bounds__(256, 1)
void gru_persistent_kernel(const float* __restrict__ gx,
                           const float* __restrict__ Whh,
                           const float* __restrict__ bhh,
                           float* __restrict__ hbuf,
                           float* __restrict__ P)
{
    extern __shared__ float sm[];
    float* ht  = sm;                          // [32][516]
    float* wsm = sm + 32 * HT_STRIDE;         // [48][514]  row = uu*3+g
    float* red = wsm + 48 * W_STRIDE;         // [8][1536]  partials; red[0..1535] reused as Gsum

    const int tid = threadIdx.x;
    const int wid = tid >> 5, lane = tid & 31;
    const int bq = lane & 3, rq = lane >> 2;
    const int bg = blockIdx.x & 3, ug = blockIdx.x >> 2;
    const int bbase = bg * 32;
    const int ubase = ug * 16;
    const int kbase = wid * 64;

    // load W slice once (persistent across steps)
    for (int f = tid; f < 48 * 256; f += 256) {
        int row = f >> 8, c2 = f & 255;
        int uu = row / 3, g = row - uu * 3;
        *(float2*)&wsm[row * W_STRIDE + c2 * 2] =
            *(const float2*)&Whh[(size_t)(g * 512 + ubase + uu) * 512 + c2 * 2];
    }

    // per-thread update-phase constants (2 outputs per thread)
    int ub[2], uu2[2];
    float bh0[2], bh1[2], bh2[2];
#pragma unroll
    for (int s = 0; s < 2; s++) {
        int idx = tid + 256 * s;
        ub[s] = idx >> 4;            // local batch row
        uu2[s] = idx & 15;           // local unit
        int d = ubase + uu2[s];
        bh0[s] = bhh[d]; bh1[s] = bhh[512 + d]; bh2[s] = bhh[1024 + d];
    }

    for (int t = 0; t < HALF; t++) {
        // ---- load h tile [32][512] (zeros at t=0) ----
        if (t == 0) {
            float4 z = make_float4(0.f, 0.f, 0.f, 0.f);
            for (int f = tid; f < 32 * 128; f += 256) {
                int row = f >> 7, c4 = f & 127;
                *(float4*)&ht[row * HT_STRIDE + c4 * 4] = z;
            }
        } else {
            const float* hsrc = hbuf + (t & 1) * (BB * DD);
            for (int f = tid; f < 32 * 128; f += 256) {
                int row = f >> 7, c4 = f & 127;
                *(float4*)&ht[row * HT_STRIDE + c4 * 4] =
                    *(const float4*)&hsrc[(size_t)(bbase + row) * DD + c4 * 4];
            }
        }
        __syncthreads();

        // ---- warp k-slice GEMM: 8 batch x 6 rows per thread, k-packed f32x2 ----
        ull acc[6][8];
#pragma unroll
        for (int j = 0; j < 6; j++)
#pragma unroll
            for (int i = 0; i < 8; i++) acc[j][i] = 0ull;

        const float* wrow = wsm + (rq * 6) * W_STRIDE + kbase;
        const float* hrow = ht + bq * HT_STRIDE + kbase;

#pragma unroll 4
        for (int kk = 0; kk < 64; kk += 2) {
            ull h2[8], w2[6];
#pragma unroll
            for (int i = 0; i < 8; i++)
                h2[i] = *(const ull*)&hrow[i * 4 * HT_STRIDE + kk];
#pragma unroll
            for (int j = 0; j < 6; j++)
                w2[j] = *(const ull*)&wrow[j * W_STRIDE + kk];
#pragma unroll
            for (int j = 0; j < 6; j++)
#pragma unroll
                for (int i = 0; i < 8; i++)
                    ffma2(acc[j][i], w2[j], h2[i]);
        }

        // ---- write partials ----
#pragma unroll
        for (int j = 0; j < 6; j++)
#pragma unroll
            for (int i = 0; i < 8; i++) {
                float2 v = un2(acc[j][i]);
                red[wid * 1536 + (bq + 4 * i) * 48 + (rq * 6 + j)] = v.x + v.y;
            }
        __syncthreads();

        // ---- reduce 8 partials; write Gsum into red[0..1535] (disjoint per thread) ----
#pragma unroll
        for (int s = 0; s < 6; s++) {
            int o = tid + 256 * s;
            float v = red[o];
#pragma unroll
            for (int w = 1; w < 8; w++) v += red[w * 1536 + o];
            red[o] = v;
        }
        __syncthreads();

        // ---- gate math + update ----
        float* hdst = hbuf + ((t + 1) & 1) * (BB * DD);
        const float* gxt = gx + (size_t)t * BB * G3D;
#pragma unroll
        for (int s = 0; s < 2; s++) {
            int b = ub[s], u = uu2[s];
            int d = ubase + u;
            int gb = bbase + b;
            float hr = red[b * 48 + u * 3 + 0] + bh0[s];
            float hz = red[b * 48 + u * 3 + 1] + bh1[s];
            float hn = red[b * 48 + u * 3 + 2] + bh2[s];
            const float* gxp = gxt + (size_t)gb * G3D + d;
            float xr = gxp[0], xz = gxp[512], xn = gxp[1024];
            float rg = 1.f / (1.f + expf(-(xr + hr)));
            float zg = 1.f / (1.f + expf(-(xz + hz)));
            float ng = tanhf(xn + rg * hn);
            float hp = ht[b * HT_STRIDE + d];
            float hnew = (1.f - zg) * ng + zg * hp;
            hdst[(size_t)gb * DD + d] = hnew;
            P[((size_t)gb * HALF + t) * DD + d] = hnew;
        }

        // ---- grid barrier (monotonic counter; all 128 CTAs resident) ----
        if (t < HALF - 1) {
            __threadfence();
            __syncthreads();
            if (tid == 0) {
                unsigned target = (unsigned)GRID_GRU * (unsigned)(t + 1);
                unsigned prev = atomicAdd(&g_arrive, 1u);
                if (prev == target - 1) {
                    atomicExch(&g_gen, (unsigned)(t + 1));
                } else {
                    unsigned v;
                    do {
                        asm volatile("ld.acquire.gpu.u32 %0, [%1];"
                                     : "=r"(v) : "l"(&g_gen) : "memory");
                        if (v < (unsigned)(t + 1)) __nanosleep(32);
                    } while (v < (unsigned)(t + 1));
                }
            }
            __syncthreads();
        }
    }
}

// ---------------- small kernels ----------------
__global__ void bar_init_kernel() { g_arrive = 0u; g_gen = 0u; }

__global__ __launch_bounds__(256)
void lse_kernel(const float* __restrict__ X, float* __restrict__ lse) {
    int warp = threadIdx.x >> 5, lane = threadIdx.x & 31;
    int row = blockIdx.x * 8 + warp;
    const float* x = X + (size_t)row * 512;
    float v[16];
#pragma unroll
    for (int i = 0; i < 4; i++) {
        float4 f = *(const float4*)&x[lane * 4 + i * 128];
        v[i * 4 + 0] = f.x; v[i * 4 + 1] = f.y; v[i * 4 + 2] = f.z; v[i * 4 + 3] = f.w;
    }
    float m = v[0];
#pragma unroll
    for (int i = 1; i < 16; i++) m = fmaxf(m, v[i]);
#pragma unroll
    for (int o = 16; o; o >>= 1) m = fmaxf(m, __shfl_xor_sync(0xffffffffu, m, o));
    float s = 0.f;
#pragma unroll
    for (int i = 0; i < 16; i++) s += expf(v[i] - m);
#pragma unroll
    for (int o = 16; o; o >>= 1) s += __shfl_xor_sync(0xffffffffu, s, o);
    if (lane == 0) lse[row] = m + logf(s);
}

__global__ void ssum_kernel(const float* __restrict__ Wh, float* __restrict__ s) {
    int j = threadIdx.x;   // 256
    float acc = 0.f;
    for (int k = 0; k < 512; k++) acc += Wh[(size_t)j * 512 + k];
    s[j] = acc;
}

__global__ __launch_bounds__(256)
void head_kernel(const float* __restrict__ H, const float* __restrict__ Wout,
                 const float* __restrict__ bout, float* __restrict__ out) {
    __shared__ float Ws[7][256];
    int tid = threadIdx.x;
    for (int f = tid; f < 7 * 256; f += 256) Ws[f >> 8][f & 255] = Wout[f];
    __syncthreads();
    int warp = tid >> 5, lane = tid & 31;
    int row = blockIdx.x * 8 + warp;
    const float* h = H + (size_t)row * 256;
    float hv[8];
    *(float4*)&hv[0] = *(const float4*)&h[lane * 8];
    *(float4*)&hv[4] = *(const float4*)&h[lane * 8 + 4];
#pragma unroll
    for (int c = 0; c < 7; c++) {
        float a = 0.f;
#pragma unroll
        for (int j = 0; j < 8; j++) a += hv[j] * Ws[c][lane * 8 + j];
#pragma unroll
        for (int o = 16; o; o >>= 1) a += __shfl_xor_sync(0xffffffffu, a, o);
        if (lane == c) out[(size_t)row * 7 + c] = a + bout[c];
    }
}

// ---------------- launch ----------------
extern "C" void kernel_launch(void* const* d_in, const int* in_sizes, int n_in,
                              void* d_out, int out_size)
{
    const float* x0   = (const float*)d_in[0];
    const float* W_ih = (const float*)d_in[3];
    const float* W_hh = (const float*)d_in[4];
    const float* b_ih = (const float*)d_in[5];
    const float* b_hh = (const float*)d_in[6];
    const float* W1   = (const float*)d_in[7];
    const float* b1   = (const float*)d_in[8];
    const float* W2   = (const float*)d_in[9];
    const float* b2   = (const float*)d_in[10];
    const float* W3   = (const float*)d_in[11];
    const float* b3   = (const float*)d_in[12];
    const float* Wh   = (const float*)d_in[13];
    const float* bh   = (const float*)d_in[14];
    const float* Wo   = (const float*)d_in[15];
    const float* bo   = (const float*)d_in[16];
    float* out = (float*)d_out;

    float *gx, *P, *t1, *t2, *h4, *lse, *s, *hbuf;
    cudaGetSymbolAddress((void**)&gx,  g_gx);
    cudaGetSymbolAddress((void**)&P,   g_P);
    cudaGetSymbolAddress((void**)&t1,  g_t1);
    cudaGetSymbolAddress((void**)&t2,  g_t2);
    cudaGetSymbolAddress((void**)&h4,  g_h4);
    cudaGetSymbolAddress((void**)&lse, g_lse);
    cudaGetSymbolAddress((void**)&s,   g_s);
    cudaGetSymbolAddress((void**)&hbuf, g_h);

    const int GRU_SMEM = (32 * HT_STRIDE + 48 * W_STRIDE + 8 * 1536) * 4;  // 213,888 B
    cudaFuncSetAttribute(gru_persistent_kernel,
                         cudaFuncAttributeMaxDynamicSharedMemorySize, GRU_SMEM);

    // reset barrier counters (deterministic per call)
    bar_init_kernel<<<1, 1>>>();

    // gx = x0[:, :256, :] @ W_ih^T + b_ih   (rows ordered r = t*128 + b)
    gemm_kernel<1, 0><<<dim3(12, 256), 256>>>(x0, W_ih, b_ih, gx, MROWS, G3D, DD, nullptr, nullptr);

    // GRU recurrence: one persistent launch, 256 steps internally
    gru_persistent_kernel<<<GRID_GRU, 256, GRU_SMEM>>>(gx, W_hh, b_hh, hbuf, P);

    // FFN
    gemm_kernel<0, 1><<<dim3(4, 256), 256>>>(P,  W1, b1, t1, MROWS, DD, DD, nullptr, nullptr);
    gemm_kernel<0, 1><<<dim3(4, 256), 256>>>(t1, W2, b2, t2, MROWS, DD, DD, nullptr, nullptr);
    gemm_kernel<0, 0><<<dim3(4, 256), 256>>>(t2, W3, b3, t1, MROWS, DD, DD, nullptr, nullptr);

    // folded log_softmax + half head
    lse_kernel<<<4096, 256>>>(t1, lse);
    ssum_kernel<<<1, 256>>>(Wh, s);
    gemm_kernel<0, 3><<<dim3(2, 256), 256>>>(t1, Wh, bh, h4, MROWS, DD / 2, DD, lse, s);

    // final head -> out [32768, 7]
    head_kernel<<<4096, 256>>>(h4, Wo, bo, out);
}

// round 4
// speedup vs baseline: 1.9746x; 1.5039x over previous
#include <cuda_runtime.h>
#include <cstdint>

// Problem constants
#define BB 128
#define TT 512
#define HALF 256
#define DD 512
#define G3D 1536
#define MROWS 32768   // BB*HALF
#define GRID_GRU 128

#define HT_STRIDE 516
#define W_STRIDE  514
#define ASTR 36       // smem row stride (f32) for tf32 GEMM tiles

typedef unsigned long long ull;

// ---------------- scratch (static device allocations; no cudaMalloc) ----------------
__device__ float g_gx[(size_t)HALF * BB * G3D];   // [256,128,1536] input preacts (incl b_ih)
__device__ float g_P [(size_t)MROWS * DD];        // emotions, row = b*256+t
__device__ float g_t1[(size_t)MROWS * DD];
__device__ float g_t2[(size_t)MROWS * DD];
__device__ float g_h4[(size_t)MROWS * (DD/2)];
__device__ float g_lse[MROWS];
__device__ float g_s[DD/2];
__device__ float g_h[2 * BB * DD];                // ping-pong hidden state
__device__ unsigned g_arrive;
__device__ unsigned g_gen;

// ---------------- f32x2 helpers (GRU) ----------------
__device__ __forceinline__ void ffma2(ull &d, ull a, ull b) {
    asm("fma.rn.f32x2 %0, %1, %2, %0;" : "+l"(d) : "l"(a), "l"(b));
}
__device__ __forceinline__ float2 un2(ull v) {
    float2 f; asm("mov.b64 {%0, %1}, %2;" : "=f"(f.x), "=f"(f.y) : "l"(v)); return f;
}

// ---------------- tf32 mma helpers ----------------
__device__ __forceinline__ float tf32r(float x) {
    uint32_t y; asm("cvt.rna.tf32.f32 %0, %1;" : "=r"(y) : "f"(x));
    return __uint_as_float(y);
}
__device__ __forceinline__ float4 tf32r4(float4 v) {
    return make_float4(tf32r(v.x), tf32r(v.y), tf32r(v.z), tf32r(v.w));
}
__device__ __forceinline__ void ldmat_x4(uint32_t addr, uint32_t &r0, uint32_t &r1,
                                         uint32_t &r2, uint32_t &r3) {
    asm volatile("ldmatrix.sync.aligned.m8n8.x4.shared.b16 {%0,%1,%2,%3}, [%4];"
                 : "=r"(r0), "=r"(r1), "=r"(r2), "=r"(r3) : "r"(addr));
}
__device__ __forceinline__ void mma_tf32(float* d, const uint32_t* a, uint32_t b0, uint32_t b1) {
    asm volatile("mma.sync.aligned.m16n8k8.row.col.f32.tf32.tf32.f32 "
                 "{%0,%1,%2,%3},{%4,%5,%6,%7},{%8,%9},{%0,%1,%2,%3};"
                 : "+f"(d[0]), "+f"(d[1]), "+f"(d[2]), "+f"(d[3])
                 : "r"(a[0]), "r"(a[1]), "r"(a[2]), "r"(a[3]), "r"(b0), "r"(b1));
}

// ---------------- tf32 tensor-core GEMM: C[M,N] = A[M,K] @ W[N,K]^T ----------------
// 128x128 tile, BK=32, 8 warps (4 m x 2 n), warp tile 32m x 64n.
// MODE_A: 0 = A row-major (lda=K); 1 = A is x0[B,T,D], logical row r -> b=r%128, t=r/128
// ACT: 0 = +bias ; 1 = tanh(+bias) ; 3 = +bias - lse[row]*s[col]
template<int MODE_A, int ACT>
__global__ __launch_bounds__(256)
void gemm_tc(const float* __restrict__ A, const float* __restrict__ W,
             const float* __restrict__ bias, float* __restrict__ C,
             int M, int N, int K,
             const float* __restrict__ lse, const float* __restrict__ svec)
{
    __shared__ float A_s[128 * ASTR];
    __shared__ float W_s[128 * ASTR];

    const int tid = threadIdx.x;
    const int wid = tid >> 5, lane = tid & 31;
    const int m0 = blockIdx.y * 128;
    const int n0 = blockIdx.x * 128;
    const int mw = (wid & 3) * 32;        // warp m offset
    const int nw = (wid >> 2) * 64;       // warp n offset

    // per-thread load coords: 4 float4 each for A and W per 32-k chunk
    int lrow[4], lc4[4];
    const float* aptr[4];
    const float* wptr[4];
#pragma unroll
    for (int i = 0; i < 4; i++) {
        int f = tid + i * 256;
        lrow[i] = f >> 3; lc4[i] = f & 7;
        int gr = m0 + lrow[i];
        if (MODE_A == 1) {
            int b = gr & 127, t = gr >> 7;
            aptr[i] = A + ((size_t)b * TT + t) * DD;
        } else {
            aptr[i] = A + (size_t)gr * K;
        }
        wptr[i] = W + (size_t)(n0 + lrow[i]) * K;
    }

    float acc[2][8][4];
#pragma unroll
    for (int mi = 0; mi < 2; mi++)
#pragma unroll
        for (int nb = 0; nb < 8; nb++)
#pragma unroll
            for (int c = 0; c < 4; c++) acc[mi][nb][c] = 0.f;

    // ldmatrix smem byte addresses
    const uint32_t a_base = (uint32_t)__cvta_generic_to_shared(A_s);
    const uint32_t w_base = (uint32_t)__cvta_generic_to_shared(W_s);
    // A: rows mw + mi*16 + (lane&15), koff = (lane>>4)*4 + kk16 + ks*8
    const int a_row = (lane & 15);
    const int a_k4  = (lane >> 4) * 4;
    // W: rows nw + nb*8 + (lane&7), koff = (lane>>3)*4 + kk16
    const int w_row = (lane & 7);
    const int w_k4  = (lane >> 3) * 4;

    // preload chunk 0
    float4 an[4], wn[4];
#pragma unroll
    for (int i = 0; i < 4; i++) {
        an[i] = *(const float4*)(aptr[i] + lc4[i] * 4);
        wn[i] = *(const float4*)(wptr[i] + lc4[i] * 4);
    }

    for (int kt = 0; kt < K; kt += 32) {
        // convert + store current chunk
#pragma unroll
        for (int i = 0; i < 4; i++) {
            *(float4*)&A_s[lrow[i] * ASTR + lc4[i] * 4] = tf32r4(an[i]);
            *(float4*)&W_s[lrow[i] * ASTR + lc4[i] * 4] = tf32r4(wn[i]);
        }
        __syncthreads();

        // prefetch next chunk (overlaps compute)
        if (kt + 32 < K) {
#pragma unroll
            for (int i = 0; i < 4; i++) {
                an[i] = *(const float4*)(aptr[i] + kt + 32 + lc4[i] * 4);
                wn[i] = *(const float4*)(wptr[i] + kt + 32 + lc4[i] * 4);
            }
        }

        // compute: 2 k16 groups
#pragma unroll
        for (int kk = 0; kk < 32; kk += 16) {
            uint32_t a[2][2][4];
#pragma unroll
            for (int mi = 0; mi < 2; mi++)
#pragma unroll
                for (int ks = 0; ks < 2; ks++) {
                    uint32_t addr = a_base +
                        (((mw + mi * 16 + a_row) * ASTR + a_k4 + kk + ks * 8) << 2);
                    ldmat_x4(addr, a[mi][ks][0], a[mi][ks][1], a[mi][ks][2], a[mi][ks][3]);
                }
#pragma unroll
            for (int nb = 0; nb < 8; nb++) {
                uint32_t b0, b1, b2, b3;
                uint32_t addr = w_base +
                    (((nw + nb * 8 + w_row) * ASTR + w_k4 + kk) << 2);
                ldmat_x4(addr, b0, b1, b2, b3);
#pragma unroll
                for (int mi = 0; mi < 2; mi++) {
                    mma_tf32(acc[mi][nb], a[mi][0], b0, b1);
                    mma_tf32(acc[mi][nb], a[mi][1], b2, b3);
                }
            }
        }
        __syncthreads();
    }

    // epilogue
#pragma unroll
    for (int mi = 0; mi < 2; mi++) {
        int r0 = m0 + mw + mi * 16 + (lane >> 2);
        float ls0 = 0.f, ls1 = 0.f;
        if (ACT == 3) { ls0 = lse[r0]; ls1 = lse[r0 + 8]; }
#pragma unroll
        for (int nb = 0; nb < 8; nb++) {
            int col = n0 + nw + nb * 8 + (lane & 3) * 2;
            float b0v = bias[col], b1v = bias[col + 1];
            float2 v0 = make_float2(acc[mi][nb][0] + b0v, acc[mi][nb][1] + b1v);
            float2 v1 = make_float2(acc[mi][nb][2] + b0v, acc[mi][nb][3] + b1v);
            if (ACT == 1) {
                v0.x = tanhf(v0.x); v0.y = tanhf(v0.y);
                v1.x = tanhf(v1.x); v1.y = tanhf(v1.y);
            }
            if (ACT == 3) {
                float s0 = svec[col], s1 = svec[col + 1];
                v0.x -= ls0 * s0; v0.y -= ls0 * s1;
                v1.x -= ls1 * s0; v1.y -= ls1 * s1;
            }
            *(float2*)&C[(size_t)r0 * N + col] = v0;
            *(float2*)&C[(size_t)(r0 + 8) * N + col] = v1;
        }
    }
}

// ---------------- persistent GRU kernel: all 256 steps in one launch ----------------
__global__ __launch_bounds__(256, 1)
void gru_persistent_kernel(const float* __restrict__ gx,
                           const float* __restrict__ Whh,
                           const float* __restrict__ bhh,
                           float* __restrict__ hbuf,
                           float* __restrict__ P)
{
    extern __shared__ float sm[];
    float* ht  = sm;                          // [32][516]
    float* wsm = sm + 32 * HT_STRIDE;         // [48][514]  row = uu*3+g
    float* red = wsm + 48 * W_STRIDE;         // [8][1536]  partials; red[0..1535] reused as Gsum

    const int tid = threadIdx.x;
    const int wid = tid >> 5, lane = tid & 31;
    const int bq = lane & 3, rq = lane >> 2;
    const int bg = blockIdx.x & 3, ug = blockIdx.x >> 2;
    const int bbase = bg * 32;
    const int ubase = ug * 16;
    const int kbase = wid * 64;

    // load W slice once (persistent across steps)
    for (int f = tid; f < 48 * 256; f += 256) {
        int row = f >> 8, c2 = f & 255;
        int uu = row / 3, g = row - uu * 3;
        *(float2*)&wsm[row * W_STRIDE + c2 * 2] =
            *(const float2*)&Whh[(size_t)(g * 512 + ubase + uu) * 512 + c2 * 2];
    }

    int ub[2], uu2[2];
    float bh0[2], bh1[2], bh2[2];
#pragma unroll
    for (int s = 0; s < 2; s++) {
        int idx = tid + 256 * s;
        ub[s] = idx >> 4;
        uu2[s] = idx & 15;
        int d = ubase + uu2[s];
        bh0[s] = bhh[d]; bh1[s] = bhh[512 + d]; bh2[s] = bhh[1024 + d];
    }

    for (int t = 0; t < HALF; t++) {
        // ---- prefetch gx operands early (independent of h; hides global latency) ----
        float xr[2], xz[2], xn[2];
        {
            const float* gxt = gx + (size_t)t * BB * G3D;
#pragma unroll
            for (int s = 0; s < 2; s++) {
                const float* gxp = gxt + (size_t)(bbase + ub[s]) * G3D + ubase + uu2[s];
                xr[s] = __ldg(gxp);
                xz[s] = __ldg(gxp + 512);
                xn[s] = __ldg(gxp + 1024);
            }
        }

        // ---- load h tile [32][512] (zeros at t=0) ----
        if (t == 0) {
            float4 z = make_float4(0.f, 0.f, 0.f, 0.f);
            for (int f = tid; f < 32 * 128; f += 256) {
                int row = f >> 7, c4 = f & 127;
                *(float4*)&ht[row * HT_STRIDE + c4 * 4] = z;
            }
        } else {
            const float* hsrc = hbuf + (t & 1) * (BB * DD);
            for (int f = tid; f < 32 * 128; f += 256) {
                int row = f >> 7, c4 = f & 127;
                *(float4*)&ht[row * HT_STRIDE + c4 * 4] =
                    *(const float4*)&hsrc[(size_t)(bbase + row) * DD + c4 * 4];
            }
        }
        __syncthreads();

        // ---- warp k-slice GEMM: 8 batch x 6 rows per thread, k-packed f32x2 ----
        ull acc[6][8];
#pragma unroll
        for (int j = 0; j < 6; j++)
#pragma unroll
            for (int i = 0; i < 8; i++) acc[j][i] = 0ull;

        const float* wrow = wsm + (rq * 6) * W_STRIDE + kbase;
        const float* hrow = ht + bq * HT_STRIDE + kbase;

#pragma unroll 4
        for (int kk = 0; kk < 64; kk += 2) {
            ull h2[8], w2[6];
#pragma unroll
            for (int i = 0; i < 8; i++)
                h2[i] = *(const ull*)&hrow[i * 4 * HT_STRIDE + kk];
#pragma unroll
            for (int j = 0; j < 6; j++)
                w2[j] = *(const ull*)&wrow[j * W_STRIDE + kk];
#pragma unroll
            for (int j = 0; j < 6; j++)
#pragma unroll
                for (int i = 0; i < 8; i++)
                    ffma2(acc[j][i], w2[j], h2[i]);
        }

        // ---- write partials ----
#pragma unroll
        for (int j = 0; j < 6; j++)
#pragma unroll
            for (int i = 0; i < 8; i++) {
                float2 v = un2(acc[j][i]);
                red[wid * 1536 + (bq + 4 * i) * 48 + (rq * 6 + j)] = v.x + v.y;
            }
        __syncthreads();

        // ---- reduce 8 partials ----
#pragma unroll
        for (int s = 0; s < 6; s++) {
            int o = tid + 256 * s;
            float v = red[o];
#pragma unroll
            for (int w = 1; w < 8; w++) v += red[w * 1536 + o];
            red[o] = v;
        }
        __syncthreads();

        // ---- gate math + update ----
        float* hdst = hbuf + ((t + 1) & 1) * (BB * DD);
#pragma unroll
        for (int s = 0; s < 2; s++) {
            int b = ub[s], u = uu2[s];
            int d = ubase + u;
            int gb = bbase + b;
            float hr = red[b * 48 + u * 3 + 0] + bh0[s];
            float hz = red[b * 48 + u * 3 + 1] + bh1[s];
            float hn = red[b * 48 + u * 3 + 2] + bh2[s];
            float rg = 1.f / (1.f + expf(-(xr[s] + hr)));
            float zg = 1.f / (1.f + expf(-(xz[s] + hz)));
            float ng = tanhf(xn[s] + rg * hn);
            float hp = ht[b * HT_STRIDE + d];
            float hnew = (1.f - zg) * ng + zg * hp;
            hdst[(size_t)gb * DD + d] = hnew;
            P[((size_t)gb * HALF + t) * DD + d] = hnew;
        }

        // ---- grid barrier (monotonic counter; all 128 CTAs resident) ----
        if (t < HALF - 1) {
            __threadfence();
            __syncthreads();
            if (tid == 0) {
                unsigned target = (unsigned)GRID_GRU * (unsigned)(t + 1);
                unsigned prev = atomicAdd(&g_arrive, 1u);
                if (prev == target - 1) {
                    atomicExch(&g_gen, (unsigned)(t + 1));
                } else {
                    unsigned v;
                    do {
                        asm volatile("ld.acquire.gpu.u32 %0, [%1];"
                                     : "=r"(v) : "l"(&g_gen) : "memory");
                        if (v < (unsigned)(t + 1)) __nanosleep(32);
                    } while (v < (unsigned)(t + 1));
                }
            }
            __syncthreads();
        }
    }
}

// ---------------- small kernels ----------------
__global__ void bar_init_kernel() { g_arrive = 0u; g_gen = 0u; }

__global__ __launch_bounds__(256)
void lse_kernel(const float* __restrict__ X, float* __restrict__ lse) {
    int warp = threadIdx.x >> 5, lane = threadIdx.x & 31;
    int row = blockIdx.x * 8 + warp;
    const float* x = X + (size_t)row * 512;
    float v[16];
#pragma unroll
    for (int i = 0; i < 4; i++) {
        float4 f = *(const float4*)&x[lane * 4 + i * 128];
        v[i * 4 + 0] = f.x; v[i * 4 + 1] = f.y; v[i * 4 + 2] = f.z; v[i * 4 + 3] = f.w;
    }
    float m = v[0];
#pragma unroll
    for (int i = 1; i < 16; i++) m = fmaxf(m, v[i]);
#pragma unroll
    for (int o = 16; o; o >>= 1) m = fmaxf(m, __shfl_xor_sync(0xffffffffu, m, o));
    float s = 0.f;
#pragma unroll
    for (int i = 0; i < 16; i++) s += expf(v[i] - m);
#pragma unroll
    for (int o = 16; o; o >>= 1) s += __shfl_xor_sync(0xffffffffu, s, o);
    if (lane == 0) lse[row] = m + logf(s);
}

__global__ void ssum_kernel(const float* __restrict__ Wh, float* __restrict__ s) {
    int j = threadIdx.x;   // 256
    float acc = 0.f;
    for (int k = 0; k < 512; k++) acc += Wh[(size_t)j * 512 + k];
    s[j] = acc;
}

__global__ __launch_bounds__(256)
void head_kernel(const float* __restrict__ H, const float* __restrict__ Wout,
                 const float* __restrict__ bout, float* __restrict__ out) {
    __shared__ float Ws[7][256];
    int tid = threadIdx.x;
    for (int f = tid; f < 7 * 256; f += 256) Ws[f >> 8][f & 255] = Wout[f];
    __syncthreads();
    int warp = tid >> 5, lane = tid & 31;
    int row = blockIdx.x * 8 + warp;
    const float* h = H + (size_t)row * 256;
    float hv[8];
    *(float4*)&hv[0] = *(const float4*)&h[lane * 8];
    *(float4*)&hv[4] = *(const float4*)&h[lane * 8 + 4];
#pragma unroll
    for (int c = 0; c < 7; c++) {
        float a = 0.f;
#pragma unroll
        for (int j = 0; j < 8; j++) a += hv[j] * Ws[c][lane * 8 + j];
#pragma unroll
        for (int o = 16; o; o >>= 1) a += __shfl_xor_sync(0xffffffffu, a, o);
        if (lane == c) out[(size_t)row * 7 + c] = a + bout[c];
    }
}

// ---------------- launch ----------------
extern "C" void kernel_launch(void* const* d_in, const int* in_sizes, int n_in,
                              void* d_out, int out_size)
{
    const float* x0   = (const float*)d_in[0];
    const float* W_ih = (const float*)d_in[3];
    const float* W_hh = (const float*)d_in[4];
    const float* b_ih = (const float*)d_in[5];
    const float* b_hh = (const float*)d_in[6];
    const float* W1   = (const float*)d_in[7];
    const float* b1   = (const float*)d_in[8];
    const float* W2   = (const float*)d_in[9];
    const float* b2   = (const float*)d_in[10];
    const float* W3   = (const float*)d_in[11];
    const float* b3   = (const float*)d_in[12];
    const float* Wh   = (const float*)d_in[13];
    const float* bh   = (const float*)d_in[14];
    const float* Wo   = (const float*)d_in[15];
    const float* bo   = (const float*)d_in[16];
    float* out = (float*)d_out;

    float *gx, *P, *t1, *t2, *h4, *lse, *s, *hbuf;
    cudaGetSymbolAddress((void**)&gx,  g_gx);
    cudaGetSymbolAddress((void**)&P,   g_P);
    cudaGetSymbolAddress((void**)&t1,  g_t1);
    cudaGetSymbolAddress((void**)&t2,  g_t2);
    cudaGetSymbolAddress((void**)&h4,  g_h4);
    cudaGetSymbolAddress((void**)&lse, g_lse);
    cudaGetSymbolAddress((void**)&s,   g_s);
    cudaGetSymbolAddress((void**)&hbuf, g_h);

    const int GRU_SMEM = (32 * HT_STRIDE + 48 * W_STRIDE + 8 * 1536) * 4;  // 213,888 B
    cudaFuncSetAttribute(gru_persistent_kernel,
                         cudaFuncAttributeMaxDynamicSharedMemorySize, GRU_SMEM);

    // reset barrier counters (deterministic per call)
    bar_init_kernel<<<1, 1>>>();

    // gx = x0[:, :256, :] @ W_ih^T + b_ih   (rows ordered r = t*128 + b)
    gemm_tc<1, 0><<<dim3(12, 256), 256>>>(x0, W_ih, b_ih, gx, MROWS, G3D, DD, nullptr, nullptr);

    // GRU recurrence: one persistent launch, 256 steps internally
    gru_persistent_kernel<<<GRID_GRU, 256, GRU_SMEM>>>(gx, W_hh, b_hh, hbuf, P);

    // FFN
    gemm_tc<0, 1><<<dim3(4, 256), 256>>>(P,  W1, b1, t1, MROWS, DD, DD, nullptr, nullptr);
    gemm_tc<0, 1><<<dim3(4, 256), 256>>>(t1, W2, b2, t2, MROWS, DD, DD, nullptr, nullptr);
    gemm_tc<0, 0><<<dim3(4, 256), 256>>>(t2, W3, b3, t1, MROWS, DD, DD, nullptr, nullptr);

    // folded log_softmax + half head
    lse_kernel<<<4096, 256>>>(t1, lse);
    ssum_kernel<<<1, 256>>>(Wh, s);
    gemm_tc<0, 3><<<dim3(2, 256), 256>>>(t1, Wh, bh, h4, MROWS, DD / 2, DD, lse, s);

    // final head -> out [32768, 7]
    head_kernel<<<4096, 256>>>(h4, Wo, bo, out);
}

// round 8
// speedup vs baseline: 2.5170x; 1.2747x over previous
#include <cuda_runtime.h>
#include <cstdint>

// Problem constants
#define BB 128
#define TT 512
#define HALF 256
#define DD 512
#define G3D 1536
#define MROWS 32768   // BB*HALF
#define GRID_GRU 128

#define HT2 516       // GRU h-tile smem stride (f32)
#define WS2 516       // GRU W-slice smem stride
#define ASTR 36       // GEMM smem row stride (f32)
#define GEMM_BUF (128 * ASTR)                 // floats per buffer per operand
#define GEMM_SMEM (4 * GEMM_BUF * 4)          // bytes: 2 operands x 2 buffers

typedef unsigned long long ull;

// ---------------- scratch (static device allocations; no cudaMalloc) ----------------
__device__ float g_gx[(size_t)HALF * BB * G3D];   // [256,128,1536] input preacts (incl b_ih)
__device__ float g_P [(size_t)MROWS * DD];        // emotions, row = b*256+t
__device__ float g_t1[(size_t)MROWS * DD];
__device__ float g_t2[(size_t)MROWS * DD];
__device__ float g_h4[(size_t)MROWS * (DD/2)];
__device__ float g_lse[MROWS];
__device__ float g_s[DD/2];
__device__ float g_h[2 * BB * DD];                // ping-pong hidden state
__device__ unsigned g_arrive4[4];
__device__ unsigned g_gen4[4];

// ---------------- tf32 mma helpers ----------------
__device__ __forceinline__ float tf32r(float x) {
    uint32_t y; asm("cvt.rna.tf32.f32 %0, %1;" : "=r"(y) : "f"(x));
    return __uint_as_float(y);
}
__device__ __forceinline__ float4 tf32r4(float4 v) {
    return make_float4(tf32r(v.x), tf32r(v.y), tf32r(v.z), tf32r(v.w));
}
__device__ __forceinline__ void ldmat_x4(uint32_t addr, uint32_t &r0, uint32_t &r1,
                                         uint32_t &r2, uint32_t &r3) {
    asm volatile("ldmatrix.sync.aligned.m8n8.x4.shared.b16 {%0,%1,%2,%3}, [%4];"
                 : "=r"(r0), "=r"(r1), "=r"(r2), "=r"(r3) : "r"(addr));
}
__device__ __forceinline__ void mma_tf32(float* d, const uint32_t* a, uint32_t b0, uint32_t b1) {
    asm volatile("mma.sync.aligned.m16n8k8.row.col.f32.tf32.tf32.f32 "
                 "{%0,%1,%2,%3},{%4,%5,%6,%7},{%8,%9},{%0,%1,%2,%3};"
                 : "+f"(d[0]), "+f"(d[1]), "+f"(d[2]), "+f"(d[3])
                 : "r"(a[0]), "r"(a[1]), "r"(a[2]), "r"(a[3]), "r"(b0), "r"(b1));
}

// ---------------- tf32 tensor-core GEMM: C[M,N] = A[M,K] @ W[N,K]^T ----------------
// 128x128 tile, BK=32, double-buffered DYNAMIC smem, 8 warps (4m x 2n), warp 32m x 64n.
// MODE_A: 0 = A row-major (lda=K); 1 = A is x0[B,T,D], logical row r -> b=r%128, t=r/128
// ACT: 0 = +bias ; 1 = tanh(+bias) ; 3 = +bias - lse[row]*s[col]
template<int MODE_A, int ACT>
__global__ __launch_bounds__(256)
void gemm_tc(const float* __restrict__ A, const float* __restrict__ W,
             const float* __restrict__ bias, float* __restrict__ C,
             int M, int N, int K,
             const float* __restrict__ lse, const float* __restrict__ svec)
{
    extern __shared__ float gsm[];
    float* A_s[2] = { gsm,                gsm + GEMM_BUF };
    float* W_s[2] = { gsm + 2 * GEMM_BUF, gsm + 3 * GEMM_BUF };

    const int tid = threadIdx.x;
    const int wid = tid >> 5, lane = tid & 31;
    const int m0 = blockIdx.y * 128;
    const int n0 = blockIdx.x * 128;
    const int mw = (wid & 3) * 32;
    const int nw = (wid >> 2) * 64;

    int lrow[4], lc4[4];
    const float* aptr[4];
    const float* wptr[4];
#pragma unroll
    for (int i = 0; i < 4; i++) {
        int f = tid + i * 256;
        lrow[i] = f >> 3; lc4[i] = f & 7;
        int gr = m0 + lrow[i];
        if (MODE_A == 1) {
            int b = gr & 127, t = gr >> 7;
            aptr[i] = A + ((size_t)b * TT + t) * DD;
        } else {
            aptr[i] = A + (size_t)gr * K;
        }
        wptr[i] = W + (size_t)(n0 + lrow[i]) * K;
    }

    float acc[2][8][4];
#pragma unroll
    for (int mi = 0; mi < 2; mi++)
#pragma unroll
        for (int nb = 0; nb < 8; nb++)
#pragma unroll
            for (int c = 0; c < 4; c++) acc[mi][nb][c] = 0.f;

    const int a_row = (lane & 15);
    const int a_k4  = (lane >> 4) * 4;
    const int w_row = (lane & 7);
    const int w_k4  = (lane >> 3) * 4;

    // preload chunk 0 and stage into buffer 0
    float4 an[4], wn[4];
#pragma unroll
    for (int i = 0; i < 4; i++) {
        an[i] = *(const float4*)(aptr[i] + lc4[i] * 4);
        wn[i] = *(const float4*)(wptr[i] + lc4[i] * 4);
    }
#pragma unroll
    for (int i = 0; i < 4; i++) {
        *(float4*)&A_s[0][lrow[i] * ASTR + lc4[i] * 4] = tf32r4(an[i]);
        *(float4*)&W_s[0][lrow[i] * ASTR + lc4[i] * 4] = tf32r4(wn[i]);
    }

    const int nc = K >> 5;
    for (int it = 0; it < nc; it++) {
        // prefetch next chunk into registers
        if (it + 1 < nc) {
            int kt = (it + 1) << 5;
#pragma unroll
            for (int i = 0; i < 4; i++) {
                an[i] = *(const float4*)(aptr[i] + kt + lc4[i] * 4);
                wn[i] = *(const float4*)(wptr[i] + kt + lc4[i] * 4);
            }
        }
        __syncthreads();
        // stage next chunk into the other buffer while computing on this one
        if (it + 1 < nc) {
            float* an_s = A_s[(it + 1) & 1];
            float* wn_s = W_s[(it + 1) & 1];
#pragma unroll
            for (int i = 0; i < 4; i++) {
                *(float4*)&an_s[lrow[i] * ASTR + lc4[i] * 4] = tf32r4(an[i]);
                *(float4*)&wn_s[lrow[i] * ASTR + lc4[i] * 4] = tf32r4(wn[i]);
            }
        }

        const uint32_t a_base = (uint32_t)__cvta_generic_to_shared(A_s[it & 1]);
        const uint32_t w_base = (uint32_t)__cvta_generic_to_shared(W_s[it & 1]);
#pragma unroll
        for (int kk = 0; kk < 32; kk += 16) {
            uint32_t a[2][2][4];
#pragma unroll
            for (int mi = 0; mi < 2; mi++)
#pragma unroll
                for (int ks = 0; ks < 2; ks++) {
                    uint32_t addr = a_base +
                        (((mw + mi * 16 + a_row) * ASTR + a_k4 + kk + ks * 8) << 2);
                    ldmat_x4(addr, a[mi][ks][0], a[mi][ks][1], a[mi][ks][2], a[mi][ks][3]);
                }
#pragma unroll
            for (int nb = 0; nb < 8; nb++) {
                uint32_t b0, b1, b2, b3;
                uint32_t addr = w_base +
                    (((nw + nb * 8 + w_row) * ASTR + w_k4 + kk) << 2);
                ldmat_x4(addr, b0, b1, b2, b3);
#pragma unroll
                for (int mi = 0; mi < 2; mi++) {
                    mma_tf32(acc[mi][nb], a[mi][0], b0, b1);
                    mma_tf32(acc[mi][nb], a[mi][1], b2, b3);
                }
            }
        }
    }

    // epilogue
#pragma unroll
    for (int mi = 0; mi < 2; mi++) {
        int r0 = m0 + mw + mi * 16 + (lane >> 2);
        float ls0 = 0.f, ls1 = 0.f;
        if (ACT == 3) { ls0 = lse[r0]; ls1 = lse[r0 + 8]; }
#pragma unroll
        for (int nb = 0; nb < 8; nb++) {
            int col = n0 + nw + nb * 8 + (lane & 3) * 2;
            float b0v = bias[col], b1v = bias[col + 1];
            float2 v0 = make_float2(acc[mi][nb][0] + b0v, acc[mi][nb][1] + b1v);
            float2 v1 = make_float2(acc[mi][nb][2] + b0v, acc[mi][nb][3] + b1v);
            if (ACT == 1) {
                v0.x = tanhf(v0.x); v0.y = tanhf(v0.y);
                v1.x = tanhf(v1.x); v1.y = tanhf(v1.y);
            }
            if (ACT == 3) {
                float s0 = svec[col], s1 = svec[col + 1];
                v0.x -= ls0 * s0; v0.y -= ls0 * s1;
                v1.x -= ls1 * s0; v1.y -= ls1 * s1;
            }
            *(float2*)&C[(size_t)r0 * N + col] = v0;
            *(float2*)&C[(size_t)(r0 + 8) * N + col] = v1;
        }
    }
}

// ---------------- persistent GRU: 256 steps, per-step GEMM on tensor cores ----------------
// Grid 128 = 4 batch-groups (32 rows) x 32 unit-groups (16 units = 48 gate-rows).
// W_hh slice tf32-rounded in smem once; h tile tf32-rounded per step for MMA operands;
// carried state stays exact fp32 (hp/hnext never pass through tf32).
// 8 warps k-split (64 k each); each warp does full 32m x 48n via mma; smem reduce.
__global__ __launch_bounds__(256, 1)
void gru_persistent_kernel(const float* __restrict__ gx,
                           const float* __restrict__ Whh,
                           const float* __restrict__ bhh,
                           float* __restrict__ hbuf,
                           float* __restrict__ P)
{
    extern __shared__ float sm[];
    float* htf = sm;                      // [32][516]  tf32-rounded h tile
    float* wsm = sm + 32 * HT2;           // [48][516]  tf32-rounded W slice, row j = u*3+g
    float* red = wsm + 48 * WS2;          // [8][1536]  partials; red[0..1535] = reduced sums

    const int tid = threadIdx.x;
    const int wid = tid >> 5, lane = tid & 31;
    const int bg = blockIdx.x & 3, ug = blockIdx.x >> 2;
    const int bbase = bg * 32;
    const int ubase = ug * 16;
    const int kbase = wid * 64;

    // load + tf32-round W slice once
    for (int f = tid; f < 48 * 128; f += 256) {
        int row = f >> 7, c4 = f & 127;
        int uu = row / 3, g = row - uu * 3;
        *(float4*)&wsm[row * WS2 + c4 * 4] =
            tf32r4(*(const float4*)&Whh[(size_t)(g * 512 + ubase + uu) * 512 + c4 * 4]);
    }

    // per-thread update-phase constants (2 outputs per thread)
    int ub[2], uu2[2];
    float bh0[2], bh1[2], bh2[2];
#pragma unroll
    for (int s = 0; s < 2; s++) {
        int idx = tid + 256 * s;
        ub[s] = idx >> 4;
        uu2[s] = idx & 15;
        int d = ubase + uu2[s];
        bh0[s] = bhh[d]; bh1[s] = bhh[512 + d]; bh2[s] = bhh[1024 + d];
    }

    const int a_row = (lane & 15);
    const int a_k4  = (lane >> 4) * 4;
    const int w_row = (lane & 7);
    const int w_k4  = (lane >> 3) * 4;
    const uint32_t h_base = (uint32_t)__cvta_generic_to_shared(htf);
    const uint32_t w_base = (uint32_t)__cvta_generic_to_shared(wsm);

    for (int t = 0; t < HALF; t++) {
        const float* hsrc = hbuf + (t & 1) * (BB * DD);

        // ---- early prefetch: gx operands + own previous-h values ----
        float xr[2], xz[2], xn[2], hp[2];
        {
            const float* gxt = gx + (size_t)t * BB * G3D;
#pragma unroll
            for (int s = 0; s < 2; s++) {
                const float* gxp = gxt + (size_t)(bbase + ub[s]) * G3D + ubase + uu2[s];
                xr[s] = __ldg(gxp);
                xz[s] = __ldg(gxp + 512);
                xn[s] = __ldg(gxp + 1024);
                hp[s] = (t == 0) ? 0.f
                        : __ldg(&hsrc[(size_t)(bbase + ub[s]) * DD + ubase + uu2[s]]);
            }
        }

        // ---- load h tile, tf32-round into smem ----
        if (t == 0) {
            float4 z = make_float4(0.f, 0.f, 0.f, 0.f);
            for (int f = tid; f < 32 * 128; f += 256) {
                int row = f >> 7, c4 = f & 127;
                *(float4*)&htf[row * HT2 + c4 * 4] = z;
            }
        } else {
            for (int f = tid; f < 32 * 128; f += 256) {
                int row = f >> 7, c4 = f & 127;
                *(float4*)&htf[row * HT2 + c4 * 4] =
                    tf32r4(*(const float4*)&hsrc[(size_t)(bbase + row) * DD + c4 * 4]);
            }
        }
        __syncthreads();

        // ---- warp k-slice MMA: full 32m x 48n on k in [kbase, kbase+64) ----
        float acc[2][6][4];
#pragma unroll
        for (int mi = 0; mi < 2; mi++)
#pragma unroll
            for (int nb = 0; nb < 6; nb++)
#pragma unroll
                for (int c = 0; c < 4; c++) acc[mi][nb][c] = 0.f;

#pragma unroll
        for (int kk = 0; kk < 64; kk += 16) {
            uint32_t a[2][2][4];
#pragma unroll
            for (int mi = 0; mi < 2; mi++)
#pragma unroll
                for (int ks = 0; ks < 2; ks++) {
                    uint32_t addr = h_base +
                        (((mi * 16 + a_row) * HT2 + kbase + kk + ks * 8 + a_k4) << 2);
                    ldmat_x4(addr, a[mi][ks][0], a[mi][ks][1], a[mi][ks][2], a[mi][ks][3]);
                }
#pragma unroll
            for (int nb = 0; nb < 6; nb++) {
                uint32_t b0, b1, b2, b3;
                uint32_t addr = w_base +
                    (((nb * 8 + w_row) * WS2 + kbase + kk + w_k4) << 2);
                ldmat_x4(addr, b0, b1, b2, b3);
#pragma unroll
                for (int mi = 0; mi < 2; mi++) {
                    mma_tf32(acc[mi][nb], a[mi][0], b0, b1);
                    mma_tf32(acc[mi][nb], a[mi][1], b2, b3);
                }
            }
        }

        // ---- write warp partials to red[wid][b*48 + n] ----
#pragma unroll
        for (int mi = 0; mi < 2; mi++) {
            int bl = mi * 16 + (lane >> 2);
#pragma unroll
            for (int nb = 0; nb < 6; nb++) {
                int n = nb * 8 + (lane & 3) * 2;
                *(float2*)&red[wid * 1536 + bl * 48 + n] =
                    make_float2(acc[mi][nb][0], acc[mi][nb][1]);
                *(float2*)&red[wid * 1536 + (bl + 8) * 48 + n] =
                    make_float2(acc[mi][nb][2], acc[mi][nb][3]);
            }
        }
        __syncthreads();

        // ---- reduce 8 warp partials ----
#pragma unroll
        for (int s = 0; s < 6; s++) {
            int o = tid + 256 * s;
            float v = red[o];
#pragma unroll
            for (int w = 1; w < 8; w++) v += red[w * 1536 + o];
            red[o] = v;
        }
        __syncthreads();

        // ---- gate math + update ----
        float* hdst = hbuf + ((t + 1) & 1) * (BB * DD);
#pragma unroll
        for (int s = 0; s < 2; s++) {
            int b = ub[s], u = uu2[s];
            int d = ubase + u;
            int gb = bbase + b;
            float hr = red[b * 48 + u * 3 + 0] + bh0[s];
            float hz = red[b * 48 + u * 3 + 1] + bh1[s];
            float hn = red[b * 48 + u * 3 + 2] + bh2[s];
            float rg = 1.f / (1.f + expf(-(xr[s] + hr)));
            float zg = 1.f / (1.f + expf(-(xz[s] + hz)));
            float ng = tanhf(xn[s] + rg * hn);
            float hnew = (1.f - zg) * ng + zg * hp[s];
            hdst[(size_t)gb * DD + d] = hnew;
            P[((size_t)gb * HALF + t) * DD + d] = hnew;
        }

        // ---- per-batch-group grid barrier (32 CTAs each; groups are independent) ----
        if (t < HALF - 1) {
            __threadfence();
            __syncthreads();
            if (tid == 0) {
                unsigned target = 32u * (unsigned)(t + 1);
                unsigned prev = atomicAdd(&g_arrive4[bg], 1u);
                if (prev == target - 1) {
                    // release store pairs with waiters' acquire loads and publishes
                    // all arrivers' prior writes.
                    asm volatile("st.release.gpu.u32 [%0], %1;"
                                 :: "l"(&g_gen4[bg]), "r"((unsigned)(t + 1)) : "memory");
                } else {
                    unsigned v;
                    do {
                        asm volatile("ld.acquire.gpu.u32 %0, [%1];"
                                     : "=r"(v) : "l"(&g_gen4[bg]) : "memory");
                        if (v < (unsigned)(t + 1)) __nanosleep(32);
                    } while (v < (unsigned)(t + 1));
                }
            }
            __syncthreads();
        }
    }
}

// ---------------- small kernels ----------------
__global__ void bar_init_kernel() {
#pragma unroll
    for (int i = 0; i < 4; i++) { g_arrive4[i] = 0u; g_gen4[i] = 0u; }
}

__global__ __launch_bounds__(256)
void lse_kernel(const float* __restrict__ X, float* __restrict__ lse) {
    int warp = threadIdx.x >> 5, lane = threadIdx.x & 31;
    int row = blockIdx.x * 8 + warp;
    const float* x = X + (size_t)row * 512;
    float v[16];
#pragma unroll
    for (int i = 0; i < 4; i++) {
        float4 f = *(const float4*)&x[lane * 4 + i * 128];
        v[i * 4 + 0] = f.x; v[i * 4 + 1] = f.y; v[i * 4 + 2] = f.z; v[i * 4 + 3] = f.w;
    }
    float m = v[0];
#pragma unroll
    for (int i = 1; i < 16; i++) m = fmaxf(m, v[i]);
#pragma unroll
    for (int o = 16; o; o >>= 1) m = fmaxf(m, __shfl_xor_sync(0xffffffffu, m, o));
    float s = 0.f;
#pragma unroll
    for (int i = 0; i < 16; i++) s += expf(v[i] - m);
#pragma unroll
    for (int o = 16; o; o >>= 1) s += __shfl_xor_sync(0xffffffffu, s, o);
    if (lane == 0) lse[row] = m + logf(s);
}

__global__ void ssum_kernel(const float* __restrict__ Wh, float* __restrict__ s) {
    int j = threadIdx.x;   // 256
    float acc = 0.f;
    for (int k = 0; k < 512; k++) acc += Wh[(size_t)j * 512 + k];
    s[j] = acc;
}

__global__ __launch_bounds__(256)
void head_kernel(const float* __restrict__ H, const float* __restrict__ Wout,
                 const float* __restrict__ bout, float* __restrict__ out) {
    __shared__ float Ws[7][256];
    int tid = threadIdx.x;
    for (int f = tid; f < 7 * 256; f += 256) Ws[f >> 8][f & 255] = Wout[f];
    __syncthreads();
    int warp = tid >> 5, lane = tid & 31;
    int row = blockIdx.x * 8 + warp;
    const float* h = H + (size_t)row * 256;
    float hv[8];
    *(float4*)&hv[0] = *(const float4*)&h[lane * 8];
    *(float4*)&hv[4] = *(const float4*)&h[lane * 8 + 4];
#pragma unroll
    for (int c = 0; c < 7; c++) {
        float a = 0.f;
#pragma unroll
        for (int j = 0; j < 8; j++) a += hv[j] * Ws[c][lane * 8 + j];
#pragma unroll
        for (int o = 16; o; o >>= 1) a += __shfl_xor_sync(0xffffffffu, a, o);
        if (lane == c) out[(size_t)row * 7 + c] = a + bout[c];
    }
}

// ---------------- launch ----------------
extern "C" void kernel_launch(void* const* d_in, const int* in_sizes, int n_in,
                              void* d_out, int out_size)
{
    const float* x0   = (const float*)d_in[0];
    const float* W_ih = (const float*)d_in[3];
    const float* W_hh = (const float*)d_in[4];
    const float* b_ih = (const float*)d_in[5];
    const float* b_hh = (const float*)d_in[6];
    const float* W1   = (const float*)d_in[7];
    const float* b1   = (const float*)d_in[8];
    const float* W2   = (const float*)d_in[9];
    const float* b2   = (const float*)d_in[10];
    const float* W3   = (const float*)d_in[11];
    const float* b3   = (const float*)d_in[12];
    const float* Wh   = (const float*)d_in[13];
    const float* bh   = (const float*)d_in[14];
    const float* Wo   = (const float*)d_in[15];
    const float* bo   = (const float*)d_in[16];
    float* out = (float*)d_out;

    float *gx, *P, *t1, *t2, *h4, *lse, *s, *hbuf;
    cudaGetSymbolAddress((void**)&gx,  g_gx);
    cudaGetSymbolAddress((void**)&P,   g_P);
    cudaGetSymbolAddress((void**)&t1,  g_t1);
    cudaGetSymbolAddress((void**)&t2,  g_t2);
    cudaGetSymbolAddress((void**)&h4,  g_h4);
    cudaGetSymbolAddress((void**)&lse, g_lse);
    cudaGetSymbolAddress((void**)&s,   g_s);
    cudaGetSymbolAddress((void**)&hbuf, g_h);

    const int GRU_SMEM = (32 * HT2 + 48 * WS2 + 8 * 1536) * 4;  // 214,272 B
    cudaFuncSetAttribute(gru_persistent_kernel,
                         cudaFuncAttributeMaxDynamicSharedMemorySize, GRU_SMEM);
    cudaFuncSetAttribute(gemm_tc<1, 0>,
                         cudaFuncAttributeMaxDynamicSharedMemorySize, GEMM_SMEM);
    cudaFuncSetAttribute(gemm_tc<0, 0>,
                         cudaFuncAttributeMaxDynamicSharedMemorySize, GEMM_SMEM);
    cudaFuncSetAttribute(gemm_tc<0, 1>,
                         cudaFuncAttributeMaxDynamicSharedMemorySize, GEMM_SMEM);
    cudaFuncSetAttribute(gemm_tc<0, 3>,
                         cudaFuncAttributeMaxDynamicSharedMemorySize, GEMM_SMEM);

    // reset barrier counters (deterministic per call)
    bar_init_kernel<<<1, 1>>>();

    // gx = x0[:, :256, :] @ W_ih^T + b_ih   (rows ordered r = t*128 + b)
    gemm_tc<1, 0><<<dim3(12, 256), 256, GEMM_SMEM>>>(x0, W_ih, b_ih, gx, MROWS, G3D, DD, nullptr, nullptr);

    // GRU recurrence: one persistent launch, 256 steps internally
    gru_persistent_kernel<<<GRID_GRU, 256, GRU_SMEM>>>(gx, W_hh, b_hh, hbuf, P);

    // FFN
    gemm_tc<0, 1><<<dim3(4, 256), 256, GEMM_SMEM>>>(P,  W1, b1, t1, MROWS, DD, DD, nullptr, nullptr);
    gemm_tc<0, 1><<<dim3(4, 256), 256, GEMM_SMEM>>>(t1, W2, b2, t2, MROWS, DD, DD, nullptr, nullptr);
    gemm_tc<0, 0><<<dim3(4, 256), 256, GEMM_SMEM>>>(t2, W3, b3, t1, MROWS, DD, DD, nullptr, nullptr);

    // folded log_softmax + half head
    lse_kernel<<<4096, 256>>>(t1, lse);
    ssum_kernel<<<1, 256>>>(Wh, s);
    gemm_tc<0, 3><<<dim3(2, 256), 256, GEMM_SMEM>>>(t1, Wh, bh, h4, MROWS, DD / 2, DD, lse, s);

    // final head -> out [32768, 7]
    head_kernel<<<4096, 256>>>(h4, Wo, bo, out);
}